// round 12
// baseline (speedup 1.0000x reference)
#include <cuda_runtime.h>
#include <cuda_bf16.h>
#include <math.h>
#include <stdint.h>

// ---------------- problem constants ----------------
#define Bb   4
#define Ll   2048
#define Dd   1024
#define Ee   8
#define FFf  4096
#define F_TOT (Bb*Ll)            // 8192
#define CAP   2560               // int(8192*2/8*1.25)

#if defined(__CUDA_ARCH_FEAT_SM103_ALL) || defined(__CUDA_ARCH_SPECIFIC__)
#define HAS_TCGEN05 1
#else
#define HAS_TCGEN05 0
#endif

// ---------------- scratch ----------------
__device__ int   g_topi [F_TOT * 2];
__device__ float g_gate [F_TOT * 2];
__device__ int   g_pos  [F_TOT * 2];
__device__ int   g_disp [Ee * CAP];
__device__ int   g_count[Ee];
__device__ __nv_bfloat16 g_xin_h[(size_t)Ee * CAP * Dd];
__device__ __nv_bfloat16 g_xin_l[(size_t)Ee * CAP * Dd];
__device__ __nv_bfloat16 g_w1t_h[(size_t)Ee * FFf * Dd];
__device__ __nv_bfloat16 g_w1t_l[(size_t)Ee * FFf * Dd];
__device__ __nv_bfloat16 g_w2t_h[(size_t)Ee * Dd * FFf];
__device__ __nv_bfloat16 g_w2t_l[(size_t)Ee * Dd * FFf];
__device__ __nv_bfloat16 g_h_h  [(size_t)Ee * CAP * FFf];
__device__ __nv_bfloat16 g_h_l  [(size_t)Ee * CAP * FFf];
__device__ float         g_out2 [(size_t)Ee * CAP * Dd];

// ---------------- helpers ----------------
__device__ __forceinline__ uint32_t smem_u32(const void* p) {
    uint32_t a;
    asm("{ .reg .u64 t; cvta.to.shared.u64 t, %1; cvt.u32.u64 %0, t; }" : "=r"(a) : "l"(p));
    return a;
}
#define CP_COMMIT() asm volatile("cp.async.commit_group;" ::: "memory")
#define SW128(o) ((o) ^ ((((uint32_t)(o)) >> 3) & 0x70))

#define MBAR_WAIT(mbar, par) do {                                             \
    asm volatile("{\n\t.reg .pred P1;\n\t"                                    \
        "WL_%=:\n\t"                                                          \
        "mbarrier.try_wait.parity.acquire.cta.shared::cta.b64 P1, [%0], %1, 0x989680;\n\t" \
        "@P1 bra.uni WD_%=;\n\tbra.uni WL_%=;\n\tWD_%=:\n\t}"                \
        :: "r"(mbar), "r"(par) : "memory");                                   \
} while (0)

// ---------------- 1. gating ----------------
__global__ void gating_kernel(const float* __restrict__ x,
                              const float* __restrict__ noise,
                              const float* __restrict__ Wg, const float* __restrict__ bg,
                              const float* __restrict__ Wn, const float* __restrict__ bn)
{
    int warp = (blockIdx.x * blockDim.x + threadIdx.x) >> 5;
    int lane = threadIdx.x & 31;
    if (warp >= F_TOT) return;
    const float* xr = x + (size_t)warp * Dd;
    float ag[Ee], an[Ee];
#pragma unroll
    for (int e = 0; e < Ee; e++) { ag[e] = 0.f; an[e] = 0.f; }
    for (int d = lane; d < Dd; d += 32) {
        float xv = xr[d];
#pragma unroll
        for (int e = 0; e < Ee; e++) {
            ag[e] = fmaf(xv, Wg[d * Ee + e], ag[e]);
            an[e] = fmaf(xv, Wn[d * Ee + e], an[e]);
        }
    }
#pragma unroll
    for (int off = 16; off > 0; off >>= 1)
#pragma unroll
        for (int e = 0; e < Ee; e++) {
            ag[e] += __shfl_down_sync(0xffffffffu, ag[e], off);
            an[e] += __shfl_down_sync(0xffffffffu, an[e], off);
        }
    if (lane == 0) {
        float noisy[Ee];
#pragma unroll
        for (int e = 0; e < Ee; e++) {
            float l  = ag[e] + bg[e];
            float nl = an[e] + bn[e];
            float sp = fmaxf(nl, 0.f) + log1pf(expf(-fabsf(nl)));
            noisy[e] = l + noise[(size_t)warp * Ee + e] * sp;
        }
        int i0 = 0;
#pragma unroll
        for (int e = 1; e < Ee; e++) if (noisy[e] > noisy[i0]) i0 = e;
        int i1 = -1;
#pragma unroll
        for (int e = 0; e < Ee; e++) {
            if (e == i0) continue;
            if (i1 < 0 || noisy[e] > noisy[i1]) i1 = e;
        }
        float z = expf(noisy[i1] - noisy[i0]);
        float g0 = 1.f / (1.f + z);
        g_topi[warp * 2 + 0] = i0;
        g_topi[warp * 2 + 1] = i1;
        g_gate[warp * 2 + 0] = g0;
        g_gate[warp * 2 + 1] = z * g0;
    }
}

// ---------------- 2. per-expert token-order scan ----------------
__global__ void scan_kernel()
{
    const int e = blockIdx.x;
    const int tid = threadIdx.x;
    __shared__ int sdata[256];
    __shared__ int sbase;
    if (tid == 0) sbase = 0;
    __syncthreads();
    for (int start = 0; start < F_TOT; start += 256) {
        int t = start + tid;
        int i0 = g_topi[t * 2 + 0];
        int i1 = g_topi[t * 2 + 1];
        int m = (i0 == e || i1 == e) ? 1 : 0;
        sdata[tid] = m;
        __syncthreads();
#pragma unroll
        for (int off = 1; off < 256; off <<= 1) {
            int v = (tid >= off) ? sdata[tid - off] : 0;
            __syncthreads();
            sdata[tid] += v;
            __syncthreads();
        }
        int p = sbase + sdata[tid] - 1;
        if (m) {
            int k = (i0 == e) ? 0 : 1;
            if (p < CAP) { g_disp[e * CAP + p] = t; g_pos[t * 2 + k] = p; }
            else         { g_pos[t * 2 + k] = -1; }
        }
        __syncthreads();
        if (tid == 0) sbase += sdata[255];
        __syncthreads();
    }
    if (tid == 0) g_count[e] = min(sbase, CAP);
}

// ---------------- 3. fused prep ----------------
__global__ void fused_prep_kernel(const float* __restrict__ W1, const float* __restrict__ W2,
                                  const float* __restrict__ x)
{
    int id = blockIdx.x;
    if (id < 65536) {
        __shared__ float tile[32][33];
        const float* W; __nv_bfloat16 *Th, *Tl;
        int R, C, bx, by, e;
        if (id < 32768) {
            W = W1; Th = g_w1t_h; Tl = g_w1t_l; R = Dd; C = FFf;
            bx = id & 127; by = (id >> 7) & 31; e = id >> 12;
        } else {
            id -= 32768;
            W = W2; Th = g_w2t_h; Tl = g_w2t_l; R = FFf; C = Dd;
            bx = id & 31; by = (id >> 5) & 127; e = id >> 12;
        }
        int tx = threadIdx.x & 31, ty = threadIdx.x >> 5;
        const float* We = W + (size_t)e * R * C;
        int c = bx * 32 + tx;
#pragma unroll
        for (int j = 0; j < 4; j++) {
            int r = by * 32 + ty + j * 8;
            tile[ty + j * 8][tx] = We[(size_t)r * C + c];
        }
        __syncthreads();
        int r2 = by * 32 + tx;
        size_t ebase = (size_t)e * C * R;
#pragma unroll
        for (int j = 0; j < 4; j++) {
            int c2 = bx * 32 + ty + j * 8;
            float v = tile[tx][ty + j * 8];
            __nv_bfloat16 h = __float2bfloat16(v);
            __nv_bfloat16 l = __float2bfloat16(v - __bfloat162float(h));
            Th[ebase + (size_t)c2 * R + r2] = h;
            Tl[ebase + (size_t)c2 * R + r2] = l;
        }
    } else {
        int gid = id - 65536;
        int e = gid / CAP;
        int c = gid % CAP;
        size_t base = ((size_t)e * CAP + c) * Dd + threadIdx.x * 4;
        if (c < g_count[e]) {
            int t = g_disp[e * CAP + c];
            float4 v = ((const float4*)(x + (size_t)t * Dd))[threadIdx.x];
            float vv[4] = {v.x, v.y, v.z, v.w};
#pragma unroll
            for (int q = 0; q < 4; q += 2) {
                __nv_bfloat16 h0 = __float2bfloat16(vv[q]);
                __nv_bfloat16 h1 = __float2bfloat16(vv[q + 1]);
                __nv_bfloat16 l0 = __float2bfloat16(vv[q] - __bfloat162float(h0));
                __nv_bfloat16 l1 = __float2bfloat16(vv[q + 1] - __bfloat162float(h1));
                *(__nv_bfloat162*)(g_xin_h + base + q) = __halves2bfloat162(h0, h1);
                *(__nv_bfloat162*)(g_xin_l + base + q) = __halves2bfloat162(l0, l1);
            }
        } else {
            __nv_bfloat162 z = __halves2bfloat162(__float2bfloat16(0.f), __float2bfloat16(0.f));
#pragma unroll
            for (int q = 0; q < 4; q += 2) {
                *(__nv_bfloat162*)(g_xin_h + base + q) = z;
                *(__nv_bfloat162*)(g_xin_l + base + q) = z;
            }
        }
    }
}

// ---------------- 4. persistent warp-specialized GEMM (decoupled pipeline) ----------------
// tile 128x256 per CTA, BK=64, split-bf16 (hh+hl+lh), 2 smem stages x 96KB.
// warps 0-7 consumers, warp 8 MMA-only, warps 9-11 loaders (96 threads).
// header: [0] tmem ptr; sd[2]@16/24 (MMA-done, cnt1); td[2]@32/40 (tile-done, cnt1);
//         tf[2]@48/56 (tmem-free, cnt256); dr[2]@64/72 (data-ready, cnt96).
#define PSTG 98304u

__global__ void __launch_bounds__(384, 1)
moe_gemm_persist(const __nv_bfloat16* __restrict__ Ah, const __nv_bfloat16* __restrict__ Al,
                 const __nv_bfloat16* __restrict__ Bh, const __nv_bfloat16* __restrict__ Bl,
                 const float* __restrict__ bias,
                 __nv_bfloat16* __restrict__ outH, __nv_bfloat16* __restrict__ outL,
                 float* __restrict__ outF,
                 int K, int Ntot, int mode)
{
#if HAS_TCGEN05
    extern __shared__ __align__(1024) char smem[];
    const int tid = threadIdx.x, wid = tid >> 5, lid = tid & 31;
    const int gx = Ntot >> 8;            // 256-wide N tiles
    const int gy = CAP >> 7;             // 20
    const int TT = gx * gy * Ee;
    const int S = K >> 6;
    uint32_t sb = smem_u32(smem);
    uint32_t sd[2] = {sb + 16, sb + 24};
    uint32_t td[2] = {sb + 32, sb + 40};
    uint32_t tf[2] = {sb + 48, sb + 56};
    uint32_t dr[2] = {sb + 64, sb + 72};
    if (tid == 0) {
#pragma unroll
        for (int b = 0; b < 2; b++) {
            asm volatile("mbarrier.init.shared.b64 [%0], 1;"   :: "r"(sd[b]) : "memory");
            asm volatile("mbarrier.init.shared.b64 [%0], 1;"   :: "r"(td[b]) : "memory");
            asm volatile("mbarrier.init.shared.b64 [%0], 256;" :: "r"(tf[b]) : "memory");
            asm volatile("mbarrier.init.shared.b64 [%0], 96;"  :: "r"(dr[b]) : "memory");
        }
    }
    if (wid == 8)
        asm volatile("tcgen05.alloc.cta_group::1.sync.aligned.shared::cta.b32 [%0], 512;"
                     :: "r"(sb) : "memory");
    __syncthreads();
    uint32_t tmem;
    asm volatile("ld.shared.b32 %0, [%1];" : "=r"(tmem) : "r"(sb));

    if (wid == 8) {
        // ======== MMA warp (lane 0 only issues) ========
        if (lid == 0) {
            const uint32_t IDESC = (8u << 24) | (32u << 17) | (1u << 10) | (1u << 7) | (1u << 4);
            int drPh[2] = {0, 0}, tfPh[2] = {0, 0}, tfFirst[2] = {1, 1};
            long q = 0;
            int halfUse = 0;
            for (int T = blockIdx.x; T < TT; T += gridDim.x) {
                int e = T / (gx * gy), r = T % (gx * gy), y = r / gx;
                if (y * 128 >= g_count[e]) continue;
                int half = halfUse & 1; halfUse++;
                uint32_t dacc = tmem + (uint32_t)half * 256;
                for (int s = 0; s < S; s++) {
                    int b = (int)(q & 1);
                    MBAR_WAIT(dr[b], drPh[b]); drPh[b] ^= 1;
                    if (s == 0) {
                        if (!tfFirst[half]) {
                            MBAR_WAIT(tf[half], tfPh[half]); tfPh[half] ^= 1;
                            asm volatile("tcgen05.fence::after_thread_sync;" ::: "memory");
                        } else tfFirst[half] = 0;
                    }
                    uint32_t stoff = sb + 1024 + (uint32_t)b * PSTG;
                    uint64_t base = ((uint64_t)2 << 61) | ((uint64_t)1 << 46) |
                                    ((uint64_t)64 << 32) | ((uint64_t)1 << 16);
                    uint64_t dAh = base | ((stoff >> 4) & 0x3FFF);
                    uint64_t dAl = base | (((stoff + 16384u) >> 4) & 0x3FFF);
                    uint64_t dBh = base | (((stoff + 32768u) >> 4) & 0x3FFF);
                    uint64_t dBl = base | (((stoff + 65536u) >> 4) & 0x3FFF);
#pragma unroll
                    for (int kc = 0; kc < 4; kc++) {
                        uint32_t en = (s | kc) != 0;
                        asm volatile("{ .reg .pred p; setp.ne.u32 p, %4, 0;\n\t"
                            "tcgen05.mma.cta_group::1.kind::f16 [%0], %1, %2, %3, {%5,%5,%5,%5}, p; }"
                            :: "r"(dacc), "l"(dAh + kc * 2), "l"(dBh + kc * 2), "r"(IDESC),
                               "r"(en), "r"(0u) : "memory");
                    }
#pragma unroll
                    for (int kc = 0; kc < 4; kc++)
                        asm volatile("{ .reg .pred p; setp.ne.u32 p, 1, 0;\n\t"
                            "tcgen05.mma.cta_group::1.kind::f16 [%0], %1, %2, %3, {%4,%4,%4,%4}, p; }"
                            :: "r"(dacc), "l"(dAh + kc * 2), "l"(dBl + kc * 2), "r"(IDESC), "r"(0u) : "memory");
#pragma unroll
                    for (int kc = 0; kc < 4; kc++)
                        asm volatile("{ .reg .pred p; setp.ne.u32 p, 1, 0;\n\t"
                            "tcgen05.mma.cta_group::1.kind::f16 [%0], %1, %2, %3, {%4,%4,%4,%4}, p; }"
                            :: "r"(dacc), "l"(dAl + kc * 2), "l"(dBh + kc * 2), "r"(IDESC), "r"(0u) : "memory");
                    asm volatile("tcgen05.commit.cta_group::1.mbarrier::arrive::one.shared::cluster.b64 [%0];"
                                 :: "r"(sd[b]) : "memory");
                    if (s == S - 1)
                        asm volatile("tcgen05.commit.cta_group::1.mbarrier::arrive::one.shared::cluster.b64 [%0];"
                                     :: "r"(td[half]) : "memory");
                    q++;
                }
            }
        }
    } else if (wid >= 9) {
        // ======== LOADER warps (9-11, 96 threads) ========
        const int p = tid - 288;          // 0..95
        int emT = -1, emS = 0;
        long emIdx = 0;
        for (int T = blockIdx.x; T < TT; T += gridDim.x) {
            int e = T / (gx * gy), r = T % (gx * gy), y = r / gx;
            if (y * 128 < g_count[e]) { emT = T; break; }
        }
        auto emitOne = [&]() {
            int e = emT / (gx * gy), r = emT % (gx * gy), y = r / gx, x2 = r - y * gx;
            int m0 = y * 128, n0 = x2 * 256, k0 = emS * 64;
            const __nv_bfloat16* teAh = Ah + (size_t)e * CAP * K;
            const __nv_bfloat16* teAl = Al + (size_t)e * CAP * K;
            const __nv_bfloat16* teBh = Bh + (size_t)e * Ntot * K;
            const __nv_bfloat16* teBl = Bl + (size_t)e * Ntot * K;
            uint32_t stoff = sb + 1024 + (uint32_t)(emIdx & 1) * PSTG;
#pragma unroll
            for (int i = 0; i < 64; i++) {            // 64*96 = 6144 chunks = full 96KB stage
                int c = p + i * 96;
                const __nv_bfloat16* src;
                uint32_t dst;
                if (c < 2048) {
                    int cc = c & 1023;
                    int row = cc >> 3, kc = cc & 7;
                    const __nv_bfloat16* T2 = (c < 1024) ? teAh : teAl;
                    src = T2 + (size_t)(m0 + row) * K + k0 + kc * 8;
                    dst = stoff + (c < 1024 ? 0u : 16384u) + SW128(row * 128 + kc * 16);
                } else {
                    int c2 = c - 2048;
                    int cc = c2 & 2047;
                    int row = cc >> 3, kc = cc & 7;
                    const __nv_bfloat16* T2 = (c2 < 2048) ? teBh : teBl;
                    src = T2 + (size_t)(n0 + row) * K + k0 + kc * 8;
                    dst = stoff + 32768u + (c2 < 2048 ? 0u : 32768u) + SW128(row * 128 + kc * 16);
                }
                asm volatile("cp.async.cg.shared.global [%0], [%1], 16;" :: "r"(dst), "l"(src));
            }
            CP_COMMIT();
            emIdx++;
            if (++emS == S) {
                emS = 0;
                int nT = -1;
                for (int T2 = emT + gridDim.x; T2 < TT; T2 += gridDim.x) {
                    int e2 = T2 / (gx * gy), r2 = T2 % (gx * gy), y2 = r2 / gx;
                    if (y2 * 128 < g_count[e2]) { nT = T2; break; }
                }
                emT = nT;
            }
        };

        if (emT >= 0) {
            // prime stages 0 and 1 (Q = activeTiles*S >= 16, so both exist)
            emitOne();
            emitOne();
            // signal data_ready for stage 0
            asm volatile("cp.async.wait_group 1;" ::: "memory");
            asm volatile("fence.proxy.async.shared::cta;" ::: "memory");
            asm volatile("mbarrier.arrive.shared.b64 _, [%0];" :: "r"(dr[0]) : "memory");

            int sdPh[2] = {0, 0};
            long u = 2;
            while (emT >= 0) {
                int b = (int)(u & 1);
                MBAR_WAIT(sd[b], sdPh[b]); sdPh[b] ^= 1;     // MMA(u-2) done -> buffer b reusable
                emitOne();                                    // load stage u into buffer b
                asm volatile("cp.async.wait_group 1;" ::: "memory");   // group u-1 complete
                asm volatile("fence.proxy.async.shared::cta;" ::: "memory");
                asm volatile("mbarrier.arrive.shared.b64 _, [%0];"
                             :: "r"(dr[(int)((u - 1) & 1)]) : "memory");
                u++;
            }
            // final stage's data-ready
            asm volatile("cp.async.wait_group 0;" ::: "memory");
            asm volatile("fence.proxy.async.shared::cta;" ::: "memory");
            asm volatile("mbarrier.arrive.shared.b64 _, [%0];"
                         :: "r"(dr[(int)((u - 1) & 1)]) : "memory");
        }
    } else {
        // ======== CONSUMERS (warps 0-7) ========
        int tdPh[2] = {0, 0};
        int halfUse = 0;
        int rowgrp = wid & 3;
        int colhalf = wid >> 2;
        for (int T = blockIdx.x; T < TT; T += gridDim.x) {
            int e = T / (gx * gy), r = T % (gx * gy), y = r / gx, x2 = r - y * gx;
            if (y * 128 >= g_count[e]) continue;
            int half = halfUse & 1; halfUse++;
            MBAR_WAIT(td[half], tdPh[half]); tdPh[half] ^= 1;
            asm volatile("tcgen05.fence::after_thread_sync;" ::: "memory");
            int m0 = y * 128, n0 = x2 * 256;
            const float* ebias = bias + (size_t)e * Ntot;
            int m = m0 + rowgrp * 32 + lid;
            uint32_t tb = tmem + (uint32_t)half * 256 + ((uint32_t)rowgrp << 21) + colhalf * 128;
#pragma unroll 1
            for (int ch = 0; ch < 4; ch++) {
                uint32_t rg[32];
                asm volatile("tcgen05.ld.sync.aligned.32x32b.x32.b32 "
                    "{%0, %1, %2, %3, %4, %5, %6, %7, "
                    " %8, %9, %10, %11, %12, %13, %14, %15, "
                    " %16, %17, %18, %19, %20, %21, %22, %23, "
                    " %24, %25, %26, %27, %28, %29, %30, %31}, [%32];"
                    : "=r"(rg[0]), "=r"(rg[1]), "=r"(rg[2]), "=r"(rg[3]),
                      "=r"(rg[4]), "=r"(rg[5]), "=r"(rg[6]), "=r"(rg[7]),
                      "=r"(rg[8]), "=r"(rg[9]), "=r"(rg[10]), "=r"(rg[11]),
                      "=r"(rg[12]), "=r"(rg[13]), "=r"(rg[14]), "=r"(rg[15]),
                      "=r"(rg[16]), "=r"(rg[17]), "=r"(rg[18]), "=r"(rg[19]),
                      "=r"(rg[20]), "=r"(rg[21]), "=r"(rg[22]), "=r"(rg[23]),
                      "=r"(rg[24]), "=r"(rg[25]), "=r"(rg[26]), "=r"(rg[27]),
                      "=r"(rg[28]), "=r"(rg[29]), "=r"(rg[30]), "=r"(rg[31])
                    : "r"(tb + ch * 32));
                asm volatile("tcgen05.wait::ld.sync.aligned;" ::: "memory");
                int nbase = n0 + colhalf * 128 + ch * 32;
                if (mode == 1) {
                    __nv_bfloat16* ph_ = outH + ((size_t)e * CAP + m) * Ntot + nbase;
                    __nv_bfloat16* pl_ = outL + ((size_t)e * CAP + m) * Ntot + nbase;
#pragma unroll
                    for (int j = 0; j < 32; j += 2) {
                        float v0 = __uint_as_float(rg[j])     + ebias[nbase + j];
                        float v1 = __uint_as_float(rg[j + 1]) + ebias[nbase + j + 1];
                        v0 = 0.5f * v0 * (1.f + erff(v0 * 0.70710678118654752f));
                        v1 = 0.5f * v1 * (1.f + erff(v1 * 0.70710678118654752f));
                        __nv_bfloat16 h0 = __float2bfloat16(v0);
                        __nv_bfloat16 h1 = __float2bfloat16(v1);
                        __nv_bfloat16 l0 = __float2bfloat16(v0 - __bfloat162float(h0));
                        __nv_bfloat16 l1 = __float2bfloat16(v1 - __bfloat162float(h1));
                        *(__nv_bfloat162*)(ph_ + j) = __halves2bfloat162(h0, h1);
                        *(__nv_bfloat162*)(pl_ + j) = __halves2bfloat162(l0, l1);
                    }
                } else {
                    float* po = outF + ((size_t)e * CAP + m) * Ntot + nbase;
#pragma unroll
                    for (int j = 0; j < 32; j += 4) {
                        float4 v;
                        v.x = __uint_as_float(rg[j])     + ebias[nbase + j];
                        v.y = __uint_as_float(rg[j + 1]) + ebias[nbase + j + 1];
                        v.z = __uint_as_float(rg[j + 2]) + ebias[nbase + j + 2];
                        v.w = __uint_as_float(rg[j + 3]) + ebias[nbase + j + 3];
                        *(float4*)(po + j) = v;
                    }
                }
            }
            asm volatile("tcgen05.fence::before_thread_sync;" ::: "memory");
            asm volatile("mbarrier.arrive.shared.b64 _, [%0];" :: "r"(tf[half]) : "memory");
        }
    }
    __syncthreads();
    if (wid == 8) {
        asm volatile("tcgen05.relinquish_alloc_permit.cta_group::1.sync.aligned;");
        asm volatile("tcgen05.dealloc.cta_group::1.sync.aligned.b32 %0, 512;" :: "r"(tmem));
    }
#else
    (void)Ah; (void)Al; (void)Bh; (void)Bl; (void)bias;
    (void)outH; (void)outL; (void)outF; (void)K; (void)Ntot; (void)mode;
#endif
}

// ---------------- 5. deterministic combine ----------------
__global__ void combine_kernel(float* __restrict__ out)
{
    int t = blockIdx.x;
    int i0 = g_topi[t * 2 + 0], i1 = g_topi[t * 2 + 1];
    int p0 = g_pos [t * 2 + 0], p1 = g_pos [t * 2 + 1];
    float gv0 = g_gate[t * 2 + 0], gv1 = g_gate[t * 2 + 1];
    float4 acc = make_float4(0.f, 0.f, 0.f, 0.f);
    int d4 = threadIdx.x;
    if (p0 >= 0) {
        float4 a = ((const float4*)(g_out2 + ((size_t)i0 * CAP + p0) * Dd))[d4];
        acc.x += gv0 * a.x; acc.y += gv0 * a.y; acc.z += gv0 * a.z; acc.w += gv0 * a.w;
    }
    if (p1 >= 0) {
        float4 b = ((const float4*)(g_out2 + ((size_t)i1 * CAP + p1) * Dd))[d4];
        acc.x += gv1 * b.x; acc.y += gv1 * b.y; acc.z += gv1 * b.z; acc.w += gv1 * b.w;
    }
    ((float4*)(out + (size_t)t * Dd))[d4] = acc;
}

// ---------------- launch ----------------
extern "C" void kernel_launch(void* const* d_in, const int* in_sizes, int n_in,
                              void* d_out, int out_size)
{
    const float* x     = (const float*)d_in[0];
    const float* noise = (const float*)d_in[1];
    const float* Wg    = (const float*)d_in[2];
    const float* bg    = (const float*)d_in[3];
    const float* Wn    = (const float*)d_in[4];
    const float* bn    = (const float*)d_in[5];
    const float* W1    = (const float*)d_in[6];
    const float* b1    = (const float*)d_in[7];
    const float* W2    = (const float*)d_in[8];
    const float* b2    = (const float*)d_in[9];
    float* out = (float*)d_out;

    const int GEMM_SMEM = 1024 + 2 * 98304;   // 197632
    cudaFuncSetAttribute(moe_gemm_persist,
                         cudaFuncAttributeMaxDynamicSharedMemorySize, GEMM_SMEM);

    __nv_bfloat16 *xin_h, *xin_l, *w1t_h, *w1t_l, *w2t_h, *w2t_l, *h_h, *h_l;
    float* out2;
    cudaGetSymbolAddress((void**)&xin_h, g_xin_h);
    cudaGetSymbolAddress((void**)&xin_l, g_xin_l);
    cudaGetSymbolAddress((void**)&w1t_h, g_w1t_h);
    cudaGetSymbolAddress((void**)&w1t_l, g_w1t_l);
    cudaGetSymbolAddress((void**)&w2t_h, g_w2t_h);
    cudaGetSymbolAddress((void**)&w2t_l, g_w2t_l);
    cudaGetSymbolAddress((void**)&h_h, g_h_h);
    cudaGetSymbolAddress((void**)&h_l, g_h_l);
    cudaGetSymbolAddress((void**)&out2, g_out2);

    // launches: 1 gating, 2 scan, 3 fused_prep, 4 GEMM1, 5 GEMM2, 6 combine
    gating_kernel<<<F_TOT / 8, 256>>>(x, noise, Wg, bg, Wn, bn);
    scan_kernel<<<Ee, 256>>>();
    fused_prep_kernel<<<65536 + Ee * CAP, 256>>>(W1, W2, x);

    // GEMM1: M=CAP, N=FF, K=D; bias b1; GELU; split-bf16 output
    moe_gemm_persist<<<148, 384, GEMM_SMEM>>>(
        xin_h, xin_l, w1t_h, w1t_l, b1, h_h, h_l, nullptr, Dd, FFf, 1);
    // GEMM2: M=CAP, N=D, K=FF; bias b2; fp32 output
    moe_gemm_persist<<<148, 384, GEMM_SMEM>>>(
        h_h, h_l, w2t_h, w2t_l, b2, nullptr, nullptr, out2, FFf, Dd, 0);

    combine_kernel<<<F_TOT, 256>>>(out);
}

// round 13
// speedup vs baseline: 1.0545x; 1.0545x over previous
#include <cuda_runtime.h>
#include <cuda_bf16.h>
#include <math.h>
#include <stdint.h>

// ---------------- problem constants ----------------
#define Bb   4
#define Ll   2048
#define Dd   1024
#define Ee   8
#define FFf  4096
#define F_TOT (Bb*Ll)            // 8192
#define CAP   2560               // int(8192*2/8*1.25)

#if defined(__CUDA_ARCH_FEAT_SM103_ALL) || defined(__CUDA_ARCH_SPECIFIC__)
#define HAS_TCGEN05 1
#else
#define HAS_TCGEN05 0
#endif

// ---------------- scratch ----------------
__device__ int   g_topi [F_TOT * 2];
__device__ float g_gate [F_TOT * 2];
__device__ int   g_pos  [F_TOT * 2];
__device__ int   g_disp [Ee * CAP];
__device__ int   g_count[Ee];
__device__ __nv_bfloat16 g_xin_h[(size_t)Ee * CAP * Dd];
__device__ __nv_bfloat16 g_xin_l[(size_t)Ee * CAP * Dd];
__device__ __nv_bfloat16 g_w1t_h[(size_t)Ee * FFf * Dd];
__device__ __nv_bfloat16 g_w1t_l[(size_t)Ee * FFf * Dd];
__device__ __nv_bfloat16 g_w2t_h[(size_t)Ee * Dd * FFf];
__device__ __nv_bfloat16 g_w2t_l[(size_t)Ee * Dd * FFf];
__device__ __nv_bfloat16 g_h_h  [(size_t)Ee * CAP * FFf];
__device__ __nv_bfloat16 g_h_l  [(size_t)Ee * CAP * FFf];
__device__ float         g_out2 [(size_t)Ee * CAP * Dd];

// ---------------- helpers ----------------
__device__ __forceinline__ uint32_t smem_u32(const void* p) {
    uint32_t a;
    asm("{ .reg .u64 t; cvta.to.shared.u64 t, %1; cvt.u32.u64 %0, t; }" : "=r"(a) : "l"(p));
    return a;
}
#define CP_COMMIT() asm volatile("cp.async.commit_group;" ::: "memory")
#define SW64SW(o) ((o) ^ ((((uint32_t)(o)) >> 3) & 0x30))

#define MBAR_WAIT(mbar, par) do {                                             \
    asm volatile("{\n\t.reg .pred P1;\n\t"                                    \
        "WL_%=:\n\t"                                                          \
        "mbarrier.try_wait.parity.acquire.cta.shared::cta.b64 P1, [%0], %1, 0x989680;\n\t" \
        "@P1 bra.uni WD_%=;\n\tbra.uni WL_%=;\n\tWD_%=:\n\t}"                \
        :: "r"(mbar), "r"(par) : "memory");                                   \
} while (0)

// ---------------- 1. gating ----------------
__global__ void gating_kernel(const float* __restrict__ x,
                              const float* __restrict__ noise,
                              const float* __restrict__ Wg, const float* __restrict__ bg,
                              const float* __restrict__ Wn, const float* __restrict__ bn)
{
    int warp = (blockIdx.x * blockDim.x + threadIdx.x) >> 5;
    int lane = threadIdx.x & 31;
    if (warp >= F_TOT) return;
    const float* xr = x + (size_t)warp * Dd;
    float ag[Ee], an[Ee];
#pragma unroll
    for (int e = 0; e < Ee; e++) { ag[e] = 0.f; an[e] = 0.f; }
    for (int d = lane; d < Dd; d += 32) {
        float xv = xr[d];
#pragma unroll
        for (int e = 0; e < Ee; e++) {
            ag[e] = fmaf(xv, Wg[d * Ee + e], ag[e]);
            an[e] = fmaf(xv, Wn[d * Ee + e], an[e]);
        }
    }
#pragma unroll
    for (int off = 16; off > 0; off >>= 1)
#pragma unroll
        for (int e = 0; e < Ee; e++) {
            ag[e] += __shfl_down_sync(0xffffffffu, ag[e], off);
            an[e] += __shfl_down_sync(0xffffffffu, an[e], off);
        }
    if (lane == 0) {
        float noisy[Ee];
#pragma unroll
        for (int e = 0; e < Ee; e++) {
            float l  = ag[e] + bg[e];
            float nl = an[e] + bn[e];
            float sp = fmaxf(nl, 0.f) + log1pf(expf(-fabsf(nl)));
            noisy[e] = l + noise[(size_t)warp * Ee + e] * sp;
        }
        int i0 = 0;
#pragma unroll
        for (int e = 1; e < Ee; e++) if (noisy[e] > noisy[i0]) i0 = e;
        int i1 = -1;
#pragma unroll
        for (int e = 0; e < Ee; e++) {
            if (e == i0) continue;
            if (i1 < 0 || noisy[e] > noisy[i1]) i1 = e;
        }
        float z = expf(noisy[i1] - noisy[i0]);
        float g0 = 1.f / (1.f + z);
        g_topi[warp * 2 + 0] = i0;
        g_topi[warp * 2 + 1] = i1;
        g_gate[warp * 2 + 0] = g0;
        g_gate[warp * 2 + 1] = z * g0;
    }
}

// ---------------- 2. per-expert token-order scan ----------------
__global__ void scan_kernel()
{
    const int e = blockIdx.x;
    const int tid = threadIdx.x;
    __shared__ int sdata[256];
    __shared__ int sbase;
    if (tid == 0) sbase = 0;
    __syncthreads();
    for (int start = 0; start < F_TOT; start += 256) {
        int t = start + tid;
        int i0 = g_topi[t * 2 + 0];
        int i1 = g_topi[t * 2 + 1];
        int m = (i0 == e || i1 == e) ? 1 : 0;
        sdata[tid] = m;
        __syncthreads();
#pragma unroll
        for (int off = 1; off < 256; off <<= 1) {
            int v = (tid >= off) ? sdata[tid - off] : 0;
            __syncthreads();
            sdata[tid] += v;
            __syncthreads();
        }
        int p = sbase + sdata[tid] - 1;
        if (m) {
            int k = (i0 == e) ? 0 : 1;
            if (p < CAP) { g_disp[e * CAP + p] = t; g_pos[t * 2 + k] = p; }
            else         { g_pos[t * 2 + k] = -1; }
        }
        __syncthreads();
        if (tid == 0) sbase += sdata[255];
        __syncthreads();
    }
    if (tid == 0) g_count[e] = min(sbase, CAP);
}

// ---------------- 3. fused prep ----------------
__global__ void fused_prep_kernel(const float* __restrict__ W1, const float* __restrict__ W2,
                                  const float* __restrict__ x)
{
    int id = blockIdx.x;
    if (id < 65536) {
        __shared__ float tile[32][33];
        const float* W; __nv_bfloat16 *Th, *Tl;
        int R, C, bx, by, e;
        if (id < 32768) {
            W = W1; Th = g_w1t_h; Tl = g_w1t_l; R = Dd; C = FFf;
            bx = id & 127; by = (id >> 7) & 31; e = id >> 12;
        } else {
            id -= 32768;
            W = W2; Th = g_w2t_h; Tl = g_w2t_l; R = FFf; C = Dd;
            bx = id & 31; by = (id >> 5) & 127; e = id >> 12;
        }
        int tx = threadIdx.x & 31, ty = threadIdx.x >> 5;
        const float* We = W + (size_t)e * R * C;
        int c = bx * 32 + tx;
#pragma unroll
        for (int j = 0; j < 4; j++) {
            int r = by * 32 + ty + j * 8;
            tile[ty + j * 8][tx] = We[(size_t)r * C + c];
        }
        __syncthreads();
        int r2 = by * 32 + tx;
        size_t ebase = (size_t)e * C * R;
#pragma unroll
        for (int j = 0; j < 4; j++) {
            int c2 = bx * 32 + ty + j * 8;
            float v = tile[tx][ty + j * 8];
            __nv_bfloat16 h = __float2bfloat16(v);
            __nv_bfloat16 l = __float2bfloat16(v - __bfloat162float(h));
            Th[ebase + (size_t)c2 * R + r2] = h;
            Tl[ebase + (size_t)c2 * R + r2] = l;
        }
    } else {
        int gid = id - 65536;
        int e = gid / CAP;
        int c = gid % CAP;
        size_t base = ((size_t)e * CAP + c) * Dd + threadIdx.x * 4;
        if (c < g_count[e]) {
            int t = g_disp[e * CAP + c];
            float4 v = ((const float4*)(x + (size_t)t * Dd))[threadIdx.x];
            float vv[4] = {v.x, v.y, v.z, v.w};
#pragma unroll
            for (int q = 0; q < 4; q += 2) {
                __nv_bfloat16 h0 = __float2bfloat16(vv[q]);
                __nv_bfloat16 h1 = __float2bfloat16(vv[q + 1]);
                __nv_bfloat16 l0 = __float2bfloat16(vv[q] - __bfloat162float(h0));
                __nv_bfloat16 l1 = __float2bfloat16(vv[q + 1] - __bfloat162float(h1));
                *(__nv_bfloat162*)(g_xin_h + base + q) = __halves2bfloat162(h0, h1);
                *(__nv_bfloat162*)(g_xin_l + base + q) = __halves2bfloat162(l0, l1);
            }
        } else {
            __nv_bfloat162 z = __halves2bfloat162(__float2bfloat16(0.f), __float2bfloat16(0.f));
#pragma unroll
            for (int q = 0; q < 4; q += 2) {
                *(__nv_bfloat162*)(g_xin_h + base + q) = z;
                *(__nv_bfloat162*)(g_xin_l + base + q) = z;
            }
        }
    }
}

// ---------------- 4. persistent warp-specialized GEMM, depth-4 pipeline ----------------
// tile 128x256 per CTA, BK=32, split-bf16 (hh+hl+lh), 4 smem stages x 48KB, SW64 rows.
// stage: Ah(8K)@0 Al(8K)@8192 Bh(16K)@16384 Bl(16K)@32768.
// warps 0-7 consumers, warp 8 MMA-only, warps 9-11 loaders (96 threads).
// header: [0] tmem; sd[4]@16..40 (MMA-done cnt1); td[2]@48/56 (tile-done cnt1);
//         tf[2]@64/72 (tmem-free cnt256); dr[4]@80..104 (data-ready cnt96).
#define PSTG 49152u

__global__ void __launch_bounds__(384, 1)
moe_gemm_persist(const __nv_bfloat16* __restrict__ Ah, const __nv_bfloat16* __restrict__ Al,
                 const __nv_bfloat16* __restrict__ Bh, const __nv_bfloat16* __restrict__ Bl,
                 const float* __restrict__ bias,
                 __nv_bfloat16* __restrict__ outH, __nv_bfloat16* __restrict__ outL,
                 float* __restrict__ outF,
                 int K, int Ntot, int mode)
{
#if HAS_TCGEN05
    extern __shared__ __align__(1024) char smem[];
    const int tid = threadIdx.x, wid = tid >> 5, lid = tid & 31;
    const int gx = Ntot >> 8;            // 256-wide N tiles
    const int gy = CAP >> 7;             // 20
    const int TT = gx * gy * Ee;
    const int S = K >> 5;                // BK=32
    uint32_t sb = smem_u32(smem);
    uint32_t sd[4] = {sb + 16, sb + 24, sb + 32, sb + 40};
    uint32_t td[2] = {sb + 48, sb + 56};
    uint32_t tf[2] = {sb + 64, sb + 72};
    uint32_t dr[4] = {sb + 80, sb + 88, sb + 96, sb + 104};
    if (tid == 0) {
#pragma unroll
        for (int b = 0; b < 4; b++) {
            asm volatile("mbarrier.init.shared.b64 [%0], 1;"  :: "r"(sd[b]) : "memory");
            asm volatile("mbarrier.init.shared.b64 [%0], 96;" :: "r"(dr[b]) : "memory");
        }
#pragma unroll
        for (int b = 0; b < 2; b++) {
            asm volatile("mbarrier.init.shared.b64 [%0], 1;"   :: "r"(td[b]) : "memory");
            asm volatile("mbarrier.init.shared.b64 [%0], 256;" :: "r"(tf[b]) : "memory");
        }
    }
    if (wid == 8)
        asm volatile("tcgen05.alloc.cta_group::1.sync.aligned.shared::cta.b32 [%0], 512;"
                     :: "r"(sb) : "memory");
    __syncthreads();
    uint32_t tmem;
    asm volatile("ld.shared.b32 %0, [%1];" : "=r"(tmem) : "r"(sb));

    if (wid == 8) {
        // ======== MMA warp (lane 0 issues) ========
        if (lid == 0) {
            const uint32_t IDESC = (8u << 24) | (32u << 17) | (1u << 10) | (1u << 7) | (1u << 4);
            // SW64 descriptor base: layout=4, version=1, SBO=32 (512B), LBO=1 (16B)
            const uint64_t DB = ((uint64_t)4 << 61) | ((uint64_t)1 << 46) |
                                ((uint64_t)32 << 32) | ((uint64_t)1 << 16);
            int drPh[4] = {0, 0, 0, 0}, tfPh[2] = {0, 0}, tfFirst[2] = {1, 1};
            long q = 0;
            int halfUse = 0;
            for (int T = blockIdx.x; T < TT; T += gridDim.x) {
                int e = T / (gx * gy), r = T % (gx * gy), y = r / gx;
                if (y * 128 >= g_count[e]) continue;
                int half = halfUse & 1; halfUse++;
                uint32_t dacc = tmem + (uint32_t)half * 256;
                for (int s = 0; s < S; s++) {
                    int b = (int)(q & 3);
                    MBAR_WAIT(dr[b], drPh[b]); drPh[b] ^= 1;
                    if (s == 0) {
                        if (!tfFirst[half]) {
                            MBAR_WAIT(tf[half], tfPh[half]); tfPh[half] ^= 1;
                            asm volatile("tcgen05.fence::after_thread_sync;" ::: "memory");
                        } else tfFirst[half] = 0;
                    }
                    uint32_t stoff = sb + 1024 + (uint32_t)b * PSTG;
                    uint64_t dAh = DB | ((stoff >> 4) & 0x3FFF);
                    uint64_t dAl = DB | (((stoff + 8192u) >> 4) & 0x3FFF);
                    uint64_t dBh = DB | (((stoff + 16384u) >> 4) & 0x3FFF);
                    uint64_t dBl = DB | (((stoff + 32768u) >> 4) & 0x3FFF);
#pragma unroll
                    for (int kc = 0; kc < 2; kc++) {
                        uint32_t en = (s | kc) != 0;
                        asm volatile("{ .reg .pred p; setp.ne.u32 p, %4, 0;\n\t"
                            "tcgen05.mma.cta_group::1.kind::f16 [%0], %1, %2, %3, {%5,%5,%5,%5}, p; }"
                            :: "r"(dacc), "l"(dAh + kc * 2), "l"(dBh + kc * 2), "r"(IDESC),
                               "r"(en), "r"(0u) : "memory");
                    }
#pragma unroll
                    for (int kc = 0; kc < 2; kc++)
                        asm volatile("{ .reg .pred p; setp.ne.u32 p, 1, 0;\n\t"
                            "tcgen05.mma.cta_group::1.kind::f16 [%0], %1, %2, %3, {%4,%4,%4,%4}, p; }"
                            :: "r"(dacc), "l"(dAh + kc * 2), "l"(dBl + kc * 2), "r"(IDESC), "r"(0u) : "memory");
#pragma unroll
                    for (int kc = 0; kc < 2; kc++)
                        asm volatile("{ .reg .pred p; setp.ne.u32 p, 1, 0;\n\t"
                            "tcgen05.mma.cta_group::1.kind::f16 [%0], %1, %2, %3, {%4,%4,%4,%4}, p; }"
                            :: "r"(dacc), "l"(dAl + kc * 2), "l"(dBh + kc * 2), "r"(IDESC), "r"(0u) : "memory");
                    asm volatile("tcgen05.commit.cta_group::1.mbarrier::arrive::one.shared::cluster.b64 [%0];"
                                 :: "r"(sd[b]) : "memory");
                    if (s == S - 1)
                        asm volatile("tcgen05.commit.cta_group::1.mbarrier::arrive::one.shared::cluster.b64 [%0];"
                                     :: "r"(td[half]) : "memory");
                    q++;
                }
            }
        }
    } else if (wid >= 9) {
        // ======== LOADER warps (9-11, 96 threads) ========
        const int p = tid - 288;          // 0..95
        int emT = -1, emS = 0;
        long emIdx = 0;
        for (int T = blockIdx.x; T < TT; T += gridDim.x) {
            int e = T / (gx * gy), r = T % (gx * gy), y = r / gx;
            if (y * 128 < g_count[e]) { emT = T; break; }
        }
        auto emitOne = [&]() {
            int e = emT / (gx * gy), r = emT % (gx * gy), y = r / gx, x2 = r - y * gx;
            int m0 = y * 128, n0 = x2 * 256, k0 = emS * 32;
            const __nv_bfloat16* teAh = Ah + (size_t)e * CAP * K;
            const __nv_bfloat16* teAl = Al + (size_t)e * CAP * K;
            const __nv_bfloat16* teBh = Bh + (size_t)e * Ntot * K;
            const __nv_bfloat16* teBl = Bl + (size_t)e * Ntot * K;
            uint32_t stoff = sb + 1024 + (uint32_t)(emIdx & 3) * PSTG;
#pragma unroll
            for (int i = 0; i < 32; i++) {            // 32*96 = 3072 chunks = full 48KB stage
                int c = p + i * 96;
                const __nv_bfloat16* src;
                uint32_t dst;
                if (c < 1024) {                       // A: Ah[0:512) Al[512:1024)
                    int cc = c & 511;
                    int row = cc >> 2, kc = cc & 3;   // 4 x 16B per 64B row
                    const __nv_bfloat16* T2 = (c < 512) ? teAh : teAl;
                    src = T2 + (size_t)(m0 + row) * K + k0 + kc * 8;
                    dst = stoff + (c < 512 ? 0u : 8192u) + SW64SW(row * 64 + kc * 16);
                } else {                              // B: Bh[0:1024) Bl[1024:2048)
                    int c2 = c - 1024;
                    int cc = c2 & 1023;
                    int row = cc >> 2, kc = cc & 3;
                    const __nv_bfloat16* T2 = (c2 < 1024) ? teBh : teBl;
                    src = T2 + (size_t)(n0 + row) * K + k0 + kc * 8;
                    dst = stoff + 16384u + (c2 < 1024 ? 0u : 16384u) + SW64SW(row * 64 + kc * 16);
                }
                asm volatile("cp.async.cg.shared.global [%0], [%1], 16;" :: "r"(dst), "l"(src));
            }
            CP_COMMIT();
            emIdx++;
            if (++emS == S) {
                emS = 0;
                int nT = -1;
                for (int T2 = emT + gridDim.x; T2 < TT; T2 += gridDim.x) {
                    int e2 = T2 / (gx * gy), r2 = T2 % (gx * gy), y2 = r2 / gx;
                    if (y2 * 128 < g_count[e2]) { nT = T2; break; }
                }
                emT = nT;
            }
        };

        if (emT >= 0) {
            // prime 4 stages (Q = activeTiles*S >= 32 always)
            emitOne(); emitOne(); emitOne(); emitOne();
            // groups 0,1 complete -> dr[0], dr[1]
            asm volatile("cp.async.wait_group 2;" ::: "memory");
            asm volatile("fence.proxy.async.shared::cta;" ::: "memory");
            asm volatile("mbarrier.arrive.shared.b64 _, [%0];" :: "r"(dr[0]) : "memory");
            asm volatile("mbarrier.arrive.shared.b64 _, [%0];" :: "r"(dr[1]) : "memory");

            int sdPh[4] = {0, 0, 0, 0};
            while (emT >= 0) {
                long u = emIdx;                      // stage about to be emitted
                int b = (int)(u & 3);
                MBAR_WAIT(sd[b], sdPh[b]); sdPh[b] ^= 1;   // MMA(u-4) done -> buffer reusable
                emitOne();                                  // load stage u
                asm volatile("cp.async.wait_group 2;" ::: "memory");  // group u-2 complete
                asm volatile("fence.proxy.async.shared::cta;" ::: "memory");
                asm volatile("mbarrier.arrive.shared.b64 _, [%0];"
                             :: "r"(dr[(int)((u - 2) & 3)]) : "memory");
            }
            // drain: emIdx = Q; dr signaled through Q-3
            asm volatile("cp.async.wait_group 1;" ::: "memory");
            asm volatile("fence.proxy.async.shared::cta;" ::: "memory");
            asm volatile("mbarrier.arrive.shared.b64 _, [%0];"
                         :: "r"(dr[(int)((emIdx - 2) & 3)]) : "memory");
            asm volatile("cp.async.wait_group 0;" ::: "memory");
            asm volatile("fence.proxy.async.shared::cta;" ::: "memory");
            asm volatile("mbarrier.arrive.shared.b64 _, [%0];"
                         :: "r"(dr[(int)((emIdx - 1) & 3)]) : "memory");
        }
    } else {
        // ======== CONSUMERS (warps 0-7) ========
        int tdPh[2] = {0, 0};
        int halfUse = 0;
        int rowgrp = wid & 3;
        int colhalf = wid >> 2;
        for (int T = blockIdx.x; T < TT; T += gridDim.x) {
            int e = T / (gx * gy), r = T % (gx * gy), y = r / gx, x2 = r - y * gx;
            if (y * 128 >= g_count[e]) continue;
            int half = halfUse & 1; halfUse++;
            MBAR_WAIT(td[half], tdPh[half]); tdPh[half] ^= 1;
            asm volatile("tcgen05.fence::after_thread_sync;" ::: "memory");
            int m0 = y * 128, n0 = x2 * 256;
            const float* ebias = bias + (size_t)e * Ntot;
            int m = m0 + rowgrp * 32 + lid;
            uint32_t tb = tmem + (uint32_t)half * 256 + ((uint32_t)rowgrp << 21) + colhalf * 128;
#pragma unroll 1
            for (int ch = 0; ch < 4; ch++) {
                uint32_t rg[32];
                asm volatile("tcgen05.ld.sync.aligned.32x32b.x32.b32 "
                    "{%0, %1, %2, %3, %4, %5, %6, %7, "
                    " %8, %9, %10, %11, %12, %13, %14, %15, "
                    " %16, %17, %18, %19, %20, %21, %22, %23, "
                    " %24, %25, %26, %27, %28, %29, %30, %31}, [%32];"
                    : "=r"(rg[0]), "=r"(rg[1]), "=r"(rg[2]), "=r"(rg[3]),
                      "=r"(rg[4]), "=r"(rg[5]), "=r"(rg[6]), "=r"(rg[7]),
                      "=r"(rg[8]), "=r"(rg[9]), "=r"(rg[10]), "=r"(rg[11]),
                      "=r"(rg[12]), "=r"(rg[13]), "=r"(rg[14]), "=r"(rg[15]),
                      "=r"(rg[16]), "=r"(rg[17]), "=r"(rg[18]), "=r"(rg[19]),
                      "=r"(rg[20]), "=r"(rg[21]), "=r"(rg[22]), "=r"(rg[23]),
                      "=r"(rg[24]), "=r"(rg[25]), "=r"(rg[26]), "=r"(rg[27]),
                      "=r"(rg[28]), "=r"(rg[29]), "=r"(rg[30]), "=r"(rg[31])
                    : "r"(tb + ch * 32));
                asm volatile("tcgen05.wait::ld.sync.aligned;" ::: "memory");
                int nbase = n0 + colhalf * 128 + ch * 32;
                if (mode == 1) {
                    __nv_bfloat16* ph_ = outH + ((size_t)e * CAP + m) * Ntot + nbase;
                    __nv_bfloat16* pl_ = outL + ((size_t)e * CAP + m) * Ntot + nbase;
#pragma unroll
                    for (int j = 0; j < 32; j += 2) {
                        float v0 = __uint_as_float(rg[j])     + ebias[nbase + j];
                        float v1 = __uint_as_float(rg[j + 1]) + ebias[nbase + j + 1];
                        v0 = 0.5f * v0 * (1.f + erff(v0 * 0.70710678118654752f));
                        v1 = 0.5f * v1 * (1.f + erff(v1 * 0.70710678118654752f));
                        __nv_bfloat16 h0 = __float2bfloat16(v0);
                        __nv_bfloat16 h1 = __float2bfloat16(v1);
                        __nv_bfloat16 l0 = __float2bfloat16(v0 - __bfloat162float(h0));
                        __nv_bfloat16 l1 = __float2bfloat16(v1 - __bfloat162float(h1));
                        *(__nv_bfloat162*)(ph_ + j) = __halves2bfloat162(h0, h1);
                        *(__nv_bfloat162*)(pl_ + j) = __halves2bfloat162(l0, l1);
                    }
                } else {
                    float* po = outF + ((size_t)e * CAP + m) * Ntot + nbase;
#pragma unroll
                    for (int j = 0; j < 32; j += 4) {
                        float4 v;
                        v.x = __uint_as_float(rg[j])     + ebias[nbase + j];
                        v.y = __uint_as_float(rg[j + 1]) + ebias[nbase + j + 1];
                        v.z = __uint_as_float(rg[j + 2]) + ebias[nbase + j + 2];
                        v.w = __uint_as_float(rg[j + 3]) + ebias[nbase + j + 3];
                        *(float4*)(po + j) = v;
                    }
                }
            }
            asm volatile("tcgen05.fence::before_thread_sync;" ::: "memory");
            asm volatile("mbarrier.arrive.shared.b64 _, [%0];" :: "r"(tf[half]) : "memory");
        }
    }
    __syncthreads();
    if (wid == 8) {
        asm volatile("tcgen05.relinquish_alloc_permit.cta_group::1.sync.aligned;");
        asm volatile("tcgen05.dealloc.cta_group::1.sync.aligned.b32 %0, 512;" :: "r"(tmem));
    }
#else
    (void)Ah; (void)Al; (void)Bh; (void)Bl; (void)bias;
    (void)outH; (void)outL; (void)outF; (void)K; (void)Ntot; (void)mode;
#endif
}

// ---------------- 5. deterministic combine ----------------
__global__ void combine_kernel(float* __restrict__ out)
{
    int t = blockIdx.x;
    int i0 = g_topi[t * 2 + 0], i1 = g_topi[t * 2 + 1];
    int p0 = g_pos [t * 2 + 0], p1 = g_pos [t * 2 + 1];
    float gv0 = g_gate[t * 2 + 0], gv1 = g_gate[t * 2 + 1];
    float4 acc = make_float4(0.f, 0.f, 0.f, 0.f);
    int d4 = threadIdx.x;
    if (p0 >= 0) {
        float4 a = ((const float4*)(g_out2 + ((size_t)i0 * CAP + p0) * Dd))[d4];
        acc.x += gv0 * a.x; acc.y += gv0 * a.y; acc.z += gv0 * a.z; acc.w += gv0 * a.w;
    }
    if (p1 >= 0) {
        float4 b = ((const float4*)(g_out2 + ((size_t)i1 * CAP + p1) * Dd))[d4];
        acc.x += gv1 * b.x; acc.y += gv1 * b.y; acc.z += gv1 * b.z; acc.w += gv1 * b.w;
    }
    ((float4*)(out + (size_t)t * Dd))[d4] = acc;
}

// ---------------- launch ----------------
extern "C" void kernel_launch(void* const* d_in, const int* in_sizes, int n_in,
                              void* d_out, int out_size)
{
    const float* x     = (const float*)d_in[0];
    const float* noise = (const float*)d_in[1];
    const float* Wg    = (const float*)d_in[2];
    const float* bg    = (const float*)d_in[3];
    const float* Wn    = (const float*)d_in[4];
    const float* bn    = (const float*)d_in[5];
    const float* W1    = (const float*)d_in[6];
    const float* b1    = (const float*)d_in[7];
    const float* W2    = (const float*)d_in[8];
    const float* b2    = (const float*)d_in[9];
    float* out = (float*)d_out;

    const int GEMM_SMEM = 1024 + 4 * 49152;   // 197632
    cudaFuncSetAttribute(moe_gemm_persist,
                         cudaFuncAttributeMaxDynamicSharedMemorySize, GEMM_SMEM);

    __nv_bfloat16 *xin_h, *xin_l, *w1t_h, *w1t_l, *w2t_h, *w2t_l, *h_h, *h_l;
    float* out2;
    cudaGetSymbolAddress((void**)&xin_h, g_xin_h);
    cudaGetSymbolAddress((void**)&xin_l, g_xin_l);
    cudaGetSymbolAddress((void**)&w1t_h, g_w1t_h);
    cudaGetSymbolAddress((void**)&w1t_l, g_w1t_l);
    cudaGetSymbolAddress((void**)&w2t_h, g_w2t_h);
    cudaGetSymbolAddress((void**)&w2t_l, g_w2t_l);
    cudaGetSymbolAddress((void**)&h_h, g_h_h);
    cudaGetSymbolAddress((void**)&h_l, g_h_l);
    cudaGetSymbolAddress((void**)&out2, g_out2);

    // launches: 1 gating, 2 scan, 3 fused_prep, 4 GEMM1, 5 GEMM2, 6 combine
    gating_kernel<<<F_TOT / 8, 256>>>(x, noise, Wg, bg, Wn, bn);
    scan_kernel<<<Ee, 256>>>();
    fused_prep_kernel<<<65536 + Ee * CAP, 256>>>(W1, W2, x);

    // GEMM1: M=CAP, N=FF, K=D; bias b1; GELU; split-bf16 output
    moe_gemm_persist<<<148, 384, GEMM_SMEM>>>(
        xin_h, xin_l, w1t_h, w1t_l, b1, h_h, h_l, nullptr, Dd, FFf, 1);
    // GEMM2: M=CAP, N=D, K=FF; bias b2; fp32 output
    moe_gemm_persist<<<148, 384, GEMM_SMEM>>>(
        h_h, h_l, w2t_h, w2t_l, b2, nullptr, nullptr, out2, FFf, Dd, 0);

    combine_kernel<<<F_TOT, 256>>>(out);
}